// round 15
// baseline (speedup 1.0000x reference)
#include <cuda_runtime.h>
#include <cuda_bf16.h>
#include <cuda_pipeline.h>

#define N_NODES    100000
#define OUTPUT_DIM 128
#define MAX_NNZ    2000000
#define KEEP_INV   (1.0f / 0.9f)
#define PIPE_D     8            // cp.async pipeline depth (power of 2)

// Static device scratch (no allocations allowed)
__device__ int    g_row_start[N_NODES + 1]; // CSR row pointers
__device__ float2 g_packed[MAX_NNZ];        // (v*KEEP_INV or 0, col-as-float-bits)

__device__ __forceinline__ void fill_rowptr(int rprev, int r, int i) {
    for (int x = rprev + 1; x <= r; ++x) g_row_start[x] = i;
}

// ---------------------------------------------------------------------------
// Kernel 1 (fused prologue, x4 vectorized — unchanged, known good): per nnz i
// build CSR rowptr from sorted rows and pack (keep ? v/keep_prob : 0, colbits).
// Mask dtype detected per block from the same 256-element window (identical
// answer in every block -> deterministic).
// ---------------------------------------------------------------------------
__global__ void __launch_bounds__(256)
pack_and_rowptr_kernel(const float* __restrict__ values,
                       const int*   __restrict__ rows,
                       const int*   __restrict__ cols,
                       const unsigned char* __restrict__ m,
                       int nnz)
{
    __shared__ int s_cnt[2][8];
    __shared__ int s_mode;
    {
        const int tid = threadIdx.x;
        const int n   = nnz < 256 ? nnz : 256;
        const int* mi = (const int*)m;

        int u8 = 0, i32 = 0;
        if (tid < n) {
            if (m[tid]  == 1) u8++;
            if (mi[tid] == 1) i32++;
        }
        #pragma unroll
        for (int off = 16; off > 0; off >>= 1) {
            u8  += __shfl_down_sync(0xffffffffu, u8,  off);
            i32 += __shfl_down_sync(0xffffffffu, i32, off);
        }
        const int wid = tid >> 5, lane = tid & 31;
        if (lane == 0) { s_cnt[0][wid] = u8; s_cnt[1][wid] = i32; }
        __syncthreads();
        if (tid == 0) {
            int tu8 = 0, ti32 = 0;
            #pragma unroll
            for (int w = 0; w < 8; ++w) { tu8 += s_cnt[0][w]; ti32 += s_cnt[1][w]; }
            int mode;
            if (tu8 * 4 > n * 3)       mode = 0;     // byte mask
            else if (ti32 * 4 > n * 3) mode = 1;     // int32 mask
            else                       mode = 2;     // float32 mask
            s_mode = mode;
        }
        __syncthreads();
    }
    const int mode = s_mode;

    const int base = (blockIdx.x * blockDim.x + threadIdx.x) * 4;
    if (base >= nnz) return;

    if (base + 4 <= nnz) {
        const int4   r4 = *(const int4*)(rows + base);
        const float4 v4 = *(const float4*)(values + base);
        const int4   c4 = *(const int4*)(cols + base);

        const int rprev = (base == 0) ? -1 : rows[base - 1];
        fill_rowptr(rprev, r4.x, base + 0);
        fill_rowptr(r4.x,  r4.y, base + 1);
        fill_rowptr(r4.y,  r4.z, base + 2);
        fill_rowptr(r4.z,  r4.w, base + 3);
        if (base + 4 == nnz) fill_rowptr(r4.w, N_NODES, nnz);

        bool k0, k1, k2, k3;
        if (mode == 0) {
            const uchar4 mm = *(const uchar4*)(m + base);
            k0 = mm.x != 0; k1 = mm.y != 0; k2 = mm.z != 0; k3 = mm.w != 0;
        } else if (mode == 1) {
            const int4 mm = *(const int4*)((const int*)m + base);
            k0 = mm.x != 0; k1 = mm.y != 0; k2 = mm.z != 0; k3 = mm.w != 0;
        } else {
            const float4 mm = *(const float4*)((const float*)m + base);
            k0 = mm.x != 0.0f; k1 = mm.y != 0.0f; k2 = mm.z != 0.0f; k3 = mm.w != 0.0f;
        }

        float4 p01, p23;
        p01.x = k0 ? v4.x * KEEP_INV : 0.0f;  p01.y = __int_as_float(c4.x);
        p01.z = k1 ? v4.y * KEEP_INV : 0.0f;  p01.w = __int_as_float(c4.y);
        p23.x = k2 ? v4.z * KEEP_INV : 0.0f;  p23.y = __int_as_float(c4.z);
        p23.z = k3 ? v4.w * KEEP_INV : 0.0f;  p23.w = __int_as_float(c4.w);
        float4* dst = (float4*)(g_packed + base);
        dst[0] = p01;
        dst[1] = p23;
    } else {
        for (int i = base; i < nnz; ++i) {
            const int r = rows[i];
            const int rprev = (i == 0) ? -1 : rows[i - 1];
            fill_rowptr(rprev, r, i);
            if (i == nnz - 1) fill_rowptr(r, N_NODES, nnz);

            bool keep;
            if (mode == 0)      keep = m[i] != 0;
            else if (mode == 1) keep = ((const int*)m)[i] != 0;
            else                keep = ((const float*)m)[i] != 0.0f;
            const float v = keep ? values[i] * KEEP_INV : 0.0f;
            g_packed[i] = make_float2(v, __int_as_float(cols[i]));
        }
    }
}

// ---------------------------------------------------------------------------
// Kernel 2: one warp per row, lane l owns output columns [4l, 4l+4).
//
// cp.async (LDGSTS) pipeline, depth PIPE_D=8: W-row gathers are copied
// global->smem asynchronously; in-flight data lives in SHARED MEMORY, not
// registers (the R11/R12/R13 failure mode: every register-based batching
// attempt lost to spills or occupancy). One __pipeline_commit per nnz, with
// empty commits padding short rows, keeps __pipeline_wait_prior(PIPE_D-1) a
// compile-time constant and the group-accounting invariant exact across row
// boundaries (leftover empty groups complete instantly).
//
// Issue side (iteration k): warp-uniform LDG.64 of g_packed[k+D] -> col ->
//   16B/lane cp.async into ring stage, commit.
// Consume side: wait_prior(D-1) -> stage ready; LDS.128 the W fragment,
//   re-read g_packed[k].x for v (L1 hit: line touched D iterations ago),
//   4 FFMAs. Dropped entries carry v=0 -> exact.
// Exposed full-gather latency: once per ROW (pipeline fill), not per nnz.
// Exclusive row ownership -> plain float4 store, bias fused, no atomics.
// ---------------------------------------------------------------------------
__global__ void __launch_bounds__(256)
spmm_pipelined_kernel(const float4* __restrict__ W4,     // [INPUT_DIM][32] float4
                      const float4* __restrict__ bias4,  // [32] float4
                      float4* __restrict__ out4)         // [N_NODES][32] float4
{
    __shared__ float4 sbuf[8][PIPE_D][32];   // 8 warps x 8 stages x 512B = 32KB

    const int warp = (blockIdx.x * blockDim.x + threadIdx.x) >> 5;
    const int lane = threadIdx.x & 31;
    const int wloc = threadIdx.x >> 5;
    if (warp >= N_NODES) return;

    const int s = g_row_start[warp];
    const int e = g_row_start[warp + 1];

    // ---- pipeline fill: PIPE_D commits (real copies where k < e) ----
    #pragma unroll
    for (int d = 0; d < PIPE_D; ++d) {
        const int k = s + d;
        if (k < e) {
            const float2 p = g_packed[k];                    // warp-uniform
            const float4* src = W4 + __float_as_int(p.y) * 32 + lane;
            __pipeline_memcpy_async(&sbuf[wloc][d][lane], src, 16);
        }
        __pipeline_commit();
    }

    float4 acc = bias4[lane];

    // ---- steady state: consume k, issue k+PIPE_D ----
    for (int k = s; k < e; ++k) {
        __pipeline_wait_prior(PIPE_D - 1);                   // k's copy done
        const int stage = (k - s) & (PIPE_D - 1);
        const float4 w = sbuf[wloc][stage][lane];
        const float v = g_packed[k].x;                       // L1 hit

        acc.x += v * w.x;
        acc.y += v * w.y;
        acc.z += v * w.z;
        acc.w += v * w.w;

        const int kn = k + PIPE_D;
        if (kn < e) {
            const float2 p = g_packed[kn];                   // warp-uniform
            const float4* src = W4 + __float_as_int(p.y) * 32 + lane;
            __pipeline_memcpy_async(&sbuf[wloc][stage][lane], src, 16);
        }
        __pipeline_commit();
    }

    out4[warp * 32 + lane] = acc;                            // 512B coalesced
}

// ---------------------------------------------------------------------------
// kernel_launch — inputs per setup_inputs() order:
//   0: values  float32 [NNZ]
//   1: rows    int32   [NNZ] (sorted)
//   2: cols    int32   [NNZ]
//   3: keep_mask (bool-ish, dtype auto-detected)
//   4: weights float32 [INPUT_DIM, 128]
//   5: bias    float32 [128]
// ---------------------------------------------------------------------------
extern "C" void kernel_launch(void* const* d_in, const int* in_sizes, int n_in,
                              void* d_out, int out_size)
{
    const float* values = (const float*)d_in[0];
    const int*   rows   = (const int*)  d_in[1];
    const int*   cols   = (const int*)  d_in[2];
    const void*  mask   =               d_in[3];
    const float4* W4    = (const float4*)d_in[4];
    const float4* bias4 = (const float4*)d_in[5];
    float4* out4        = (float4*)d_out;

    const int nnz = in_sizes[0];

    {
        const int threads = 256;
        const int elems_per_block = threads * 4;
        const int blocks = (nnz + elems_per_block - 1) / elems_per_block;
        pack_and_rowptr_kernel<<<blocks, threads>>>(
            values, rows, cols, (const unsigned char*)mask, nnz);
    }

    {
        const int warps_per_block = 8;                 // 256 threads
        const int blocks = (N_NODES + warps_per_block - 1) / warps_per_block;
        spmm_pipelined_kernel<<<blocks, 256>>>(W4, bias4, out4);
    }
}

// round 17
// speedup vs baseline: 1.0798x; 1.0798x over previous
#include <cuda_runtime.h>
#include <cuda_bf16.h>

#define N_NODES    100000
#define OUTPUT_DIM 128
#define MAX_NNZ    2000000
#define KEEP_INV   (1.0f / 0.9f)

// Static device scratch (no allocations allowed)
__device__ int    g_row_start[N_NODES + 1]; // CSR row pointers
__device__ float2 g_packed[MAX_NNZ];        // (v*KEEP_INV or 0, col-as-float-bits)

__device__ __forceinline__ void fill_rowptr(int rprev, int r, int i) {
    for (int x = rprev + 1; x <= r; ++x) g_row_start[x] = i;
}

// ---------------------------------------------------------------------------
// Kernel 1 (fused prologue, x4 vectorized — EXACT R11/R12 code, best measured
// pack at ~3-13us vs 19.5us scalar): per nnz i build CSR rowptr from sorted
// rows and pack (keep ? v/keep_prob : 0, colbits). Mask dtype detected per
// block from the same 256-element window (identical answer in every block ->
// deterministic, no serialized detect kernel).
// ---------------------------------------------------------------------------
__global__ void __launch_bounds__(256)
pack_and_rowptr_kernel(const float* __restrict__ values,
                       const int*   __restrict__ rows,
                       const int*   __restrict__ cols,
                       const unsigned char* __restrict__ m,
                       int nnz)
{
    // ---- per-block mask dtype detect (identical in every block) ----
    __shared__ int s_cnt[2][8];
    __shared__ int s_mode;
    {
        const int tid = threadIdx.x;
        const int n   = nnz < 256 ? nnz : 256;
        const int* mi = (const int*)m;

        int u8 = 0, i32 = 0;
        if (tid < n) {
            if (m[tid]  == 1) u8++;
            if (mi[tid] == 1) i32++;
        }
        #pragma unroll
        for (int off = 16; off > 0; off >>= 1) {
            u8  += __shfl_down_sync(0xffffffffu, u8,  off);
            i32 += __shfl_down_sync(0xffffffffu, i32, off);
        }
        const int wid = tid >> 5, lane = tid & 31;
        if (lane == 0) { s_cnt[0][wid] = u8; s_cnt[1][wid] = i32; }
        __syncthreads();
        if (tid == 0) {
            int tu8 = 0, ti32 = 0;
            #pragma unroll
            for (int w = 0; w < 8; ++w) { tu8 += s_cnt[0][w]; ti32 += s_cnt[1][w]; }
            int mode;
            if (tu8 * 4 > n * 3)       mode = 0;     // byte mask
            else if (ti32 * 4 > n * 3) mode = 1;     // int32 mask
            else                       mode = 2;     // float32 mask
            s_mode = mode;
        }
        __syncthreads();
    }
    const int mode = s_mode;

    const int base = (blockIdx.x * blockDim.x + threadIdx.x) * 4;
    if (base >= nnz) return;

    if (base + 4 <= nnz) {
        const int4   r4 = *(const int4*)(rows + base);
        const float4 v4 = *(const float4*)(values + base);
        const int4   c4 = *(const int4*)(cols + base);

        const int rprev = (base == 0) ? -1 : rows[base - 1];
        fill_rowptr(rprev, r4.x, base + 0);
        fill_rowptr(r4.x,  r4.y, base + 1);
        fill_rowptr(r4.y,  r4.z, base + 2);
        fill_rowptr(r4.z,  r4.w, base + 3);
        if (base + 4 == nnz) fill_rowptr(r4.w, N_NODES, nnz);

        bool k0, k1, k2, k3;
        if (mode == 0) {
            const uchar4 mm = *(const uchar4*)(m + base);
            k0 = mm.x != 0; k1 = mm.y != 0; k2 = mm.z != 0; k3 = mm.w != 0;
        } else if (mode == 1) {
            const int4 mm = *(const int4*)((const int*)m + base);
            k0 = mm.x != 0; k1 = mm.y != 0; k2 = mm.z != 0; k3 = mm.w != 0;
        } else {
            const float4 mm = *(const float4*)((const float*)m + base);
            k0 = mm.x != 0.0f; k1 = mm.y != 0.0f; k2 = mm.z != 0.0f; k3 = mm.w != 0.0f;
        }

        float4 p01, p23;
        p01.x = k0 ? v4.x * KEEP_INV : 0.0f;  p01.y = __int_as_float(c4.x);
        p01.z = k1 ? v4.y * KEEP_INV : 0.0f;  p01.w = __int_as_float(c4.y);
        p23.x = k2 ? v4.z * KEEP_INV : 0.0f;  p23.y = __int_as_float(c4.z);
        p23.z = k3 ? v4.w * KEEP_INV : 0.0f;  p23.w = __int_as_float(c4.w);
        float4* dst = (float4*)(g_packed + base);  // base%4==0 -> 32B aligned
        dst[0] = p01;
        dst[1] = p23;
    } else {
        for (int i = base; i < nnz; ++i) {
            const int r = rows[i];
            const int rprev = (i == 0) ? -1 : rows[i - 1];
            fill_rowptr(rprev, r, i);
            if (i == nnz - 1) fill_rowptr(r, N_NODES, nnz);

            bool keep;
            if (mode == 0)      keep = m[i] != 0;
            else if (mode == 1) keep = ((const int*)m)[i] != 0;
            else                keep = ((const float*)m)[i] != 0.0f;
            const float v = keep ? values[i] * KEEP_INV : 0.0f;
            g_packed[i] = make_float2(v, __int_as_float(cols[i]));
        }
    }
}

// ---------------------------------------------------------------------------
// Kernel 2: one warp per output row, lane l owns output columns [4l, 4l+4).
// EXACT R9 code — best measured spmm (60.4us; 32 regs, 80% occ). Per nnz:
// one warp-uniform LDG.64 of (v, colbits) — 16 nnz per 128B line, L1
// broadcast — then a warp-uniform zero-skip branch and one coalesced 512B
// W-row gather. Six structural alternatives (shfl staging, smem compaction,
// branchless unroll, explicit reg batching, two-rows, cp.async pipeline)
// all measured slower: iterations here are already independent and ptxas
// already batches what the 32-reg/80%-occ point allows.
// Exclusive row ownership -> plain float4 store, bias fused, no atomics.
// ---------------------------------------------------------------------------
__global__ void __launch_bounds__(256)
spmm_warp_per_row_kernel(const float4* __restrict__ W4,     // [INPUT_DIM][32] float4
                         const float4* __restrict__ bias4,  // [32] float4
                         float4* __restrict__ out4)         // [N_NODES][32] float4
{
    const int warp = (blockIdx.x * blockDim.x + threadIdx.x) >> 5;
    const int lane = threadIdx.x & 31;
    if (warp >= N_NODES) return;

    const int s = g_row_start[warp];
    const int e = g_row_start[warp + 1];

    float4 acc = bias4[lane];

    #pragma unroll 4
    for (int k = s; k < e; ++k) {
        const float2 p = g_packed[k];                // warp-uniform broadcast
        if (p.x != 0.0f) {                           // warp-uniform skip of dropped nnz
            const float4 w = W4[__float_as_int(p.y) * 32 + lane];
            acc.x += p.x * w.x;
            acc.y += p.x * w.y;
            acc.z += p.x * w.z;
            acc.w += p.x * w.w;
        }
    }

    out4[warp * 32 + lane] = acc;                    // 512B coalesced per warp
}

// ---------------------------------------------------------------------------
// kernel_launch — inputs per setup_inputs() order:
//   0: values  float32 [NNZ]
//   1: rows    int32   [NNZ] (sorted)
//   2: cols    int32   [NNZ]
//   3: keep_mask (bool-ish, dtype auto-detected)
//   4: weights float32 [INPUT_DIM, 128]
//   5: bias    float32 [128]
// ---------------------------------------------------------------------------
extern "C" void kernel_launch(void* const* d_in, const int* in_sizes, int n_in,
                              void* d_out, int out_size)
{
    const float* values = (const float*)d_in[0];
    const int*   rows   = (const int*)  d_in[1];
    const int*   cols   = (const int*)  d_in[2];
    const void*  mask   =               d_in[3];
    const float4* W4    = (const float4*)d_in[4];
    const float4* bias4 = (const float4*)d_in[5];
    float4* out4        = (float4*)d_out;

    const int nnz = in_sizes[0];

    {
        const int threads = 256;
        const int elems_per_block = threads * 4;
        const int blocks = (nnz + elems_per_block - 1) / elems_per_block;
        pack_and_rowptr_kernel<<<blocks, threads>>>(
            values, rows, cols, (const unsigned char*)mask, nnz);
    }

    {
        const int warps_per_block = 8;                 // 256 threads
        const int blocks = (N_NODES + warps_per_block - 1) / warps_per_block;
        spmm_warp_per_row_kernel<<<blocks, 256>>>(W4, bias4, out4);
    }
}